// round 13
// baseline (speedup 1.0000x reference)
#include <cuda_runtime.h>
#include <cstdint>

// GroupedEmbeddingBag: T tables, weights [V, D] fp32.
// values: [T, L] int32, offsets: [T, B+1] int32, out: [B, T*D] fp32.
// One WARP = one whole bag, 32-thread CTAs (resources free the instant the
// bag finishes; no sibling-warp imbalance). Double-buffered gather pipeline
// with batches of 6 rows (2x6 float4 = 48 payload regs) and
// __launch_bounds__(32,28) so the register file fits ~28 warps/SM
// (R12 showed regs=90 capped us at 22.7 warps -- the binding limit).
// Indices for 64 rows are loaded with two coalesced LDG.32s per chunk and
// shfl-broadcast to feed the gathers.

static constexpr int T = 8;
static constexpr int V = 100000;
static constexpr int D = 128;
static constexpr int B = 4096;

__device__ __forceinline__ float4 ldg_na(const void* p) {
    float4 v;
    asm volatile("ld.global.nc.L1::no_allocate.v4.f32 {%0,%1,%2,%3}, [%4];"
                 : "=f"(v.x), "=f"(v.y), "=f"(v.z), "=f"(v.w)
                 : "l"(p));
    return v;
}

__global__ void __launch_bounds__(32, 28)
grouped_embedding_bag_kernel(const int* __restrict__ values,
                             const int* __restrict__ offsets,
                             const float* __restrict__ weights,
                             float* __restrict__ out,
                             int L)
{
    const int bag  = blockIdx.x;       // 0 .. T*B-1, table-major
    const int lane = threadIdx.x;

    const int t = bag / B;
    const int b = bag - t * B;

    const int s = offsets[t * (B + 1) + b];
    const int e = offsets[t * (B + 1) + b + 1];

    const int* vals = values + t * L;
    // Per-table base; per-row byte offset fits in 32 bits (idx*512 <= 51.2MB).
    const char* __restrict__ Wb =
        reinterpret_cast<const char*>(weights + (long long)t * V * D);
    const unsigned lane_off = (unsigned)lane * 16u;

    float4 acc0 = make_float4(0.f, 0.f, 0.f, 0.f);
    float4 acc1 = make_float4(0.f, 0.f, 0.f, 0.f);

    int i = s;
    while (i < e) {
        const int m = min(60, e - i);          // chunk: 10 batches of 6
        // Two coalesced index loads, issued together (one latency window).
        const int my0 = (lane      < m) ? vals[i + lane]      : 0;
        const int my1 = (lane + 32 < m) ? vals[i + lane + 32] : 0;

        // idx for chunk-row r (clamped to m-1 for tail duplicates).
        auto get_idx = [&](int r) -> unsigned {
            const int rc  = (r < m) ? r : (m - 1);
            const int v32 = (rc < 32) ? my0 : my1;
            return (unsigned)__shfl_sync(0xffffffffu, v32, rc & 31);
        };
        auto gather6 = [&](float4* buf, int j) {
            #pragma unroll
            for (int k = 0; k < 6; k++)
                buf[k] = ldg_na(Wb + get_idx(j + k) * 512u + lane_off);
        };
        auto consume6 = [&](const float4* buf, int j) {
            #pragma unroll
            for (int k = 0; k < 6; k += 2) {
                if (j + k < m) {
                    acc0.x += buf[k].x; acc0.y += buf[k].y;
                    acc0.z += buf[k].z; acc0.w += buf[k].w;
                }
                if (j + k + 1 < m) {
                    acc1.x += buf[k+1].x; acc1.y += buf[k+1].y;
                    acc1.z += buf[k+1].z; acc1.w += buf[k+1].w;
                }
            }
        };

        float4 bufA[6], bufB[6];
        gather6(bufA, 0);
        for (int j = 0; j < m; j += 12) {
            if (j + 6 < m)  gather6(bufB, j + 6);
            consume6(bufA, j);
            if (j + 12 < m) gather6(bufA, j + 12);
            if (j + 6 < m)  consume6(bufB, j + 6);
        }
        i += m;
    }

    acc0.x += acc1.x; acc0.y += acc1.y; acc0.z += acc1.z; acc0.w += acc1.w;

    // out[b, t*D ...]: 512B contiguous, coalesced. Empty bags write zeros.
    float4* dst = reinterpret_cast<float4*>(out + (long long)b * (T * D) + t * D);
    dst[lane] = acc0;
}

extern "C" void kernel_launch(void* const* d_in, const int* in_sizes, int n_in,
                              void* d_out, int out_size)
{
    const int*   values  = (const int*)d_in[0];    // [T, L] int32
    const int*   offsets = (const int*)d_in[1];    // [T, B+1] int32
    const float* weights = (const float*)d_in[2];  // [T, V, D] fp32
    float* out = (float*)d_out;                    // [B, T*D] fp32

    const int L = in_sizes[0] / T;

    const int blocks  = T * B;   // 32768 one-warp blocks, one bag each
    const int threads = 32;

    grouped_embedding_bag_kernel<<<blocks, threads>>>(values, offsets, weights, out, L);
}